// round 4
// baseline (speedup 1.0000x reference)
#include <cuda_runtime.h>
#include <cuda_bf16.h>
#include <math.h>

#define VOCAB 32000
#define H 512
#define B 10
#define KB 431
#define KB_PAD 1523
#define KBW (KB_PAD + KB)      // 1954
#define L H                     // 512

// d_out layout (floats), concatenation of the 5 reference outputs:
#define OUT_OFF   0
#define CTX_OFF   (VOCAB * B)                 // 320000
#define HID_OFF   (CTX_OFF + B * H)           // 325120
#define ATTN_OFF  (HID_OFF + B * H)           // 330240
#define KBA_OFF   (ATTN_OFF + B * L)          // 335360
#define KBA_TOT   (B * L * KBW)               // 10004480

// scratch (no device allocation allowed)
__device__ float g_h1[B * H];
__device__ float g_concat[B * H];

__device__ __forceinline__ float dot4(float4 a, float4 b) {
    return a.x * b.x + a.y * b.y + a.z * b.z + a.w * b.w;
}

__device__ __forceinline__ float warp_sum(float v) {
#pragma unroll
    for (int o = 16; o > 0; o >>= 1) v += __shfl_xor_sync(0xFFFFFFFFu, v, o);
    return v;
}

__device__ __forceinline__ float sigmoidf_(float x) {
    return 1.0f / (1.0f + __expf(-x));
}

// ---------------------------------------------------------------------------
// Kernel 1: GRU step. grid = H blocks (one per hidden unit j), 320 threads
// (warp w = batch b). Also writes hidden output and zeros context slab.
// ---------------------------------------------------------------------------
__global__ void gru_kernel(const int* __restrict__ seq,
                           const float* __restrict__ emb,
                           const float* __restrict__ h0,
                           const float* __restrict__ w_ih,
                           const float* __restrict__ w_hh,
                           const float* __restrict__ b_ih,
                           const float* __restrict__ b_hh,
                           float* __restrict__ d_out) {
    int j = blockIdx.x;
    int b = threadIdx.x >> 5;
    int lane = threadIdx.x & 31;
    if (b >= B) return;

    const float4* x4  = (const float4*)(emb + (long)seq[b] * H);
    const float4* h4  = (const float4*)(h0 + b * H);
    const float4* wir = (const float4*)(w_ih + (long)j * H);
    const float4* wiz = (const float4*)(w_ih + (long)(H + j) * H);
    const float4* win = (const float4*)(w_ih + (long)(2 * H + j) * H);
    const float4* whr = (const float4*)(w_hh + (long)j * H);
    const float4* whz = (const float4*)(w_hh + (long)(H + j) * H);
    const float4* whn = (const float4*)(w_hh + (long)(2 * H + j) * H);

    float sir = 0.f, siz = 0.f, sin_ = 0.f, shr = 0.f, shz = 0.f, shn = 0.f;
#pragma unroll
    for (int c = lane; c < H / 4; c += 32) {
        float4 xv = x4[c], hv = h4[c];
        sir  += dot4(xv, wir[c]);
        siz  += dot4(xv, wiz[c]);
        sin_ += dot4(xv, win[c]);
        shr  += dot4(hv, whr[c]);
        shz  += dot4(hv, whz[c]);
        shn  += dot4(hv, whn[c]);
    }
    sir = warp_sum(sir);  siz = warp_sum(siz);  sin_ = warp_sum(sin_);
    shr = warp_sum(shr);  shz = warp_sum(shz);  shn  = warp_sum(shn);

    if (lane == 0) {
        float gir = sir + b_ih[j];
        float giz = siz + b_ih[H + j];
        float gin = sin_ + b_ih[2 * H + j];
        float ghr = shr + b_hh[j];
        float ghz = shz + b_hh[H + j];
        float ghn = shn + b_hh[2 * H + j];
        float r = sigmoidf_(gir + ghr);
        float z = sigmoidf_(giz + ghz);
        float n = tanhf(gin + r * ghn);
        float hprev = h0[b * H + j];
        float h1 = (1.0f - z) * n + z * hprev;
        g_h1[b * H + j] = h1;
        d_out[HID_OFF + b * H + j] = h1;
        d_out[CTX_OFF + b * H + j] = 0.0f;  // zero context for atomicAdd
    }
}

// ---------------------------------------------------------------------------
// Kernel 2 (fused): energies + softmax(axis=0) + context partial.
// grid = L/2 blocks (2 l's per block), 320 threads (warp = batch b).
// enc[l,b,:] is loaded ONCE into registers and reused for both the energy
// dot product and the context contribution a[b,l] * enc[l,b,:].
// Context accumulated in registers across the block's 2 l's, then 16 scalar
// atomicAdds per thread into the ctx slab (5120 addrs, ~256 adds each).
// ---------------------------------------------------------------------------
__global__ void __launch_bounds__(320)
attn_ctx_kernel(const float* __restrict__ enc,
                float* __restrict__ d_out) {
    int b = threadIdx.x >> 5;      // 10 warps exactly
    int lane = threadIdx.x & 31;
    __shared__ float e_s[2][B];

    const float4* h4 = (const float4*)(g_h1 + b * H);
    float4 h[4];
#pragma unroll
    for (int i = 0; i < 4; i++) h[i] = h4[lane + 32 * i];

    float4 ev[2][4];
#pragma unroll
    for (int t = 0; t < 2; t++) {
        int l = blockIdx.x * 2 + t;
        const float4* e4 = (const float4*)(enc + ((long)l * B + b) * H);
        float s = 0.f;
#pragma unroll
        for (int i = 0; i < 4; i++) {
            ev[t][i] = e4[lane + 32 * i];
            s += dot4(h[i], ev[t][i]);
        }
        s = warp_sum(s);
        if (lane == 0) e_s[t][b] = s;
    }
    __syncthreads();

    float4 acc[4];
#pragma unroll
    for (int i = 0; i < 4; i++) acc[i] = make_float4(0.f, 0.f, 0.f, 0.f);

#pragma unroll
    for (int t = 0; t < 2; t++) {
        int l = blockIdx.x * 2 + t;
        float m = -1e30f;
#pragma unroll
        for (int i = 0; i < B; i++) m = fmaxf(m, e_s[t][i]);
        float sum = 0.f;
#pragma unroll
        for (int i = 0; i < B; i++) sum += __expf(e_s[t][i] - m);
        float a = __expf(e_s[t][b] - m) / sum;
        if (lane == 0) d_out[ATTN_OFF + b * L + l] = a;
#pragma unroll
        for (int i = 0; i < 4; i++) {
            acc[i].x += a * ev[t][i].x;
            acc[i].y += a * ev[t][i].y;
            acc[i].z += a * ev[t][i].z;
            acc[i].w += a * ev[t][i].w;
        }
    }

    float* ctx = d_out + CTX_OFF + b * H;
#pragma unroll
    for (int i = 0; i < 4; i++) {
        int h0i = (lane + 32 * i) * 4;
        atomicAdd(&ctx[h0i + 0], acc[i].x);
        atomicAdd(&ctx[h0i + 1], acc[i].y);
        atomicAdd(&ctx[h0i + 2], acc[i].z);
        atomicAdd(&ctx[h0i + 3], acc[i].w);
    }
}

// ---------------------------------------------------------------------------
// Kernel 3: kb_attn. One thread per output element of the (B, L, 1954) slab.
// Reshape is a flat reinterpret: value at (b,p,1523+k) = sum_j emb_kb[idx, h]
// with f = p*431+k, kb_row = f/512, h = f%512.
// ---------------------------------------------------------------------------
__global__ void kb_kernel(const int* __restrict__ kb_inputs,
                          const float* __restrict__ emb_kb,
                          float* __restrict__ d_out) {
    unsigned t = blockIdx.x * blockDim.x + threadIdx.x;
    if (t >= (unsigned)KBA_TOT) return;
    unsigned b   = t / (L * KBW);
    unsigned rem = t % (L * KBW);
    unsigned p   = rem / KBW;
    unsigned c   = rem % KBW;
    float v = 0.0f;
    if (c >= KB_PAD) {
        unsigned f  = p * KB + (c - KB_PAD);
        unsigned kb = f >> 9;      // /512
        unsigned h  = f & 511;     // %512
        const int* idx = kb_inputs + ((long)b * KB + kb) * 3;
        v = __ldg(&emb_kb[(long)idx[0] * H + h])
          + __ldg(&emb_kb[(long)idx[1] * H + h])
          + __ldg(&emb_kb[(long)idx[2] * H + h]);
    }
    d_out[KBA_OFF + t] = v;
}

// ---------------------------------------------------------------------------
// Kernel 4: concat_output = tanh([h1, ctx] @ w_concat.T + b_concat).
// grid = H blocks, warp per batch, dot length 2H.
// ---------------------------------------------------------------------------
__global__ void concat_kernel(const float* __restrict__ w_concat,
                              const float* __restrict__ b_concat,
                              const float* __restrict__ d_out_ctx) {
    int j = blockIdx.x;
    int b = threadIdx.x >> 5;
    int lane = threadIdx.x & 31;
    if (b >= B) return;

    const float4* h4 = (const float4*)(g_h1 + b * H);
    const float4* c4 = (const float4*)(d_out_ctx + CTX_OFF + b * H);
    const float4* w4 = (const float4*)(w_concat + (long)j * 2 * H);
    float s = 0.f;
#pragma unroll
    for (int c = lane; c < H / 4; c += 32) {
        s += dot4(h4[c], w4[c]);
        s += dot4(c4[c], w4[H / 4 + c]);
    }
    s = warp_sum(s);
    if (lane == 0) g_concat[b * H + j] = tanhf(s + b_concat[j]);
}

// ---------------------------------------------------------------------------
// Kernel 5: output = concat @ w_out.T + b_out.  (10 x 512 x 32000 fp32 GEMM)
// 1000 blocks x 256 threads. concat staged in smem; warp handles 4 vocab rows
// for all 10 batches with float4 loads.
// ---------------------------------------------------------------------------
__global__ void __launch_bounds__(256)
out_kernel(const float* __restrict__ w_out,
           const float* __restrict__ b_out,
           float* __restrict__ d_out) {
    __shared__ float cs[B * H];  // 20 KB
    for (int i = threadIdx.x; i < B * H; i += 256) cs[i] = g_concat[i];
    __syncthreads();

    int warp = threadIdx.x >> 5;
    int lane = threadIdx.x & 31;
    int v0 = blockIdx.x * 32 + warp * 4;

    // hoist bias off the epilogue critical path
    float bias[4];
#pragma unroll
    for (int i = 0; i < 4; i++) bias[i] = __ldg(&b_out[v0 + i]);

    float acc[4][B];
#pragma unroll
    for (int i = 0; i < 4; i++)
#pragma unroll
        for (int bb = 0; bb < B; bb++) acc[i][bb] = 0.f;

    const float4* w0 = (const float4*)(w_out + (long)v0 * H);
    const float4* cs4 = (const float4*)cs;

#pragma unroll
    for (int c = 0; c < 4; c++) {
        int k4 = c * 32 + lane;  // float4 index within the 512-row (0..127)
        float4 wv[4];
#pragma unroll
        for (int i = 0; i < 4; i++) wv[i] = __ldg(&w0[i * (H / 4) + k4]);
#pragma unroll
        for (int bb = 0; bb < B; bb++) {
            float4 cv = cs4[bb * (H / 4) + k4];
#pragma unroll
            for (int i = 0; i < 4; i++) {
                acc[i][bb] += wv[i].x * cv.x + wv[i].y * cv.y
                            + wv[i].z * cv.z + wv[i].w * cv.w;
            }
        }
    }

#pragma unroll
    for (int i = 0; i < 4; i++) {
#pragma unroll
        for (int bb = 0; bb < B; bb++) {
            float s = warp_sum(acc[i][bb]);
            if (lane == 0)
                d_out[OUT_OFF + (long)bb * VOCAB + v0 + i] = s + bias[i];
        }
    }
}

// ---------------------------------------------------------------------------
extern "C" void kernel_launch(void* const* d_in, const int* in_sizes, int n_in,
                              void* d_out, int out_size) {
    const int*   input_seq  = (const int*)d_in[0];
    const int*   kb_inputs  = (const int*)d_in[1];
    // d_in[2] = last_context (unused by the reference math)
    const float* last_hidden = (const float*)d_in[3];
    const float* enc        = (const float*)d_in[4];
    const float* emb        = (const float*)d_in[5];
    const float* emb_kb     = (const float*)d_in[6];
    const float* w_ih       = (const float*)d_in[7];
    const float* w_hh       = (const float*)d_in[8];
    const float* b_ih       = (const float*)d_in[9];
    const float* b_hh       = (const float*)d_in[10];
    const float* w_concat   = (const float*)d_in[11];
    const float* b_concat   = (const float*)d_in[12];
    const float* w_out      = (const float*)d_in[13];
    const float* b_out      = (const float*)d_in[14];
    float* out = (float*)d_out;

    // independent KB branch first (largest kernel; no deps)
    kb_kernel<<<(KBA_TOT + 255) / 256, 256>>>(kb_inputs, emb_kb, out);

    gru_kernel<<<H, 320>>>(input_seq, emb, last_hidden,
                           w_ih, w_hh, b_ih, b_hh, out);
    attn_ctx_kernel<<<L / 2, 320>>>(enc, out);
    concat_kernel<<<H, 320>>>(w_concat, b_concat, out);
    out_kernel<<<VOCAB / 32, 256>>>(w_out, b_out, out);
}

// round 6
// speedup vs baseline: 1.1538x; 1.1538x over previous
#include <cuda_runtime.h>
#include <cuda_bf16.h>
#include <math.h>

#define VOCAB 32000
#define H 512
#define B 10
#define KB 431
#define KB_PAD 1523
#define KBW (KB_PAD + KB)      // 1954
#define L H                     // 512

// d_out layout (floats), concatenation of the 5 reference outputs:
#define OUT_OFF   0
#define CTX_OFF   (VOCAB * B)                 // 320000
#define HID_OFF   (CTX_OFF + B * H)           // 325120
#define ATTN_OFF  (HID_OFF + B * H)           // 330240
#define KBA_OFF   (ATTN_OFF + B * L)          // 335360
#define KBA_TOT   (B * L * KBW)               // 10004480

// scratch (no device allocation allowed)
__device__ float g_h1[B * H];
__device__ float g_concat[B * H];

__device__ __forceinline__ float dot4(float4 a, float4 b) {
    return a.x * b.x + a.y * b.y + a.z * b.z + a.w * b.w;
}

__device__ __forceinline__ float warp_sum(float v) {
#pragma unroll
    for (int o = 16; o > 0; o >>= 1) v += __shfl_xor_sync(0xFFFFFFFFu, v, o);
    return v;
}

__device__ __forceinline__ float sigmoidf_(float x) {
    return 1.0f / (1.0f + __expf(-x));
}

// ---------------------------------------------------------------------------
// Kernel 1: GRU step. grid = H blocks (one per hidden unit j), 320 threads
// (warp w = batch b). Also writes hidden output and zeros context slab.
// ---------------------------------------------------------------------------
__global__ void gru_kernel(const int* __restrict__ seq,
                           const float* __restrict__ emb,
                           const float* __restrict__ h0,
                           const float* __restrict__ w_ih,
                           const float* __restrict__ w_hh,
                           const float* __restrict__ b_ih,
                           const float* __restrict__ b_hh,
                           float* __restrict__ d_out) {
    int j = blockIdx.x;
    int b = threadIdx.x >> 5;
    int lane = threadIdx.x & 31;
    if (b >= B) return;

    const float4* x4  = (const float4*)(emb + (long)seq[b] * H);
    const float4* h4  = (const float4*)(h0 + b * H);
    const float4* wir = (const float4*)(w_ih + (long)j * H);
    const float4* wiz = (const float4*)(w_ih + (long)(H + j) * H);
    const float4* win = (const float4*)(w_ih + (long)(2 * H + j) * H);
    const float4* whr = (const float4*)(w_hh + (long)j * H);
    const float4* whz = (const float4*)(w_hh + (long)(H + j) * H);
    const float4* whn = (const float4*)(w_hh + (long)(2 * H + j) * H);

    float sir = 0.f, siz = 0.f, sin_ = 0.f, shr = 0.f, shz = 0.f, shn = 0.f;
#pragma unroll
    for (int c = lane; c < H / 4; c += 32) {
        float4 xv = x4[c], hv = h4[c];
        sir  += dot4(xv, wir[c]);
        siz  += dot4(xv, wiz[c]);
        sin_ += dot4(xv, win[c]);
        shr  += dot4(hv, whr[c]);
        shz  += dot4(hv, whz[c]);
        shn  += dot4(hv, whn[c]);
    }
    sir = warp_sum(sir);  siz = warp_sum(siz);  sin_ = warp_sum(sin_);
    shr = warp_sum(shr);  shz = warp_sum(shz);  shn  = warp_sum(shn);

    if (lane == 0) {
        float gir = sir + b_ih[j];
        float giz = siz + b_ih[H + j];
        float gin = sin_ + b_ih[2 * H + j];
        float ghr = shr + b_hh[j];
        float ghz = shz + b_hh[H + j];
        float ghn = shn + b_hh[2 * H + j];
        float r = sigmoidf_(gir + ghr);
        float z = sigmoidf_(giz + ghz);
        float n = tanhf(gin + r * ghn);
        float hprev = h0[b * H + j];
        float h1 = (1.0f - z) * n + z * hprev;
        g_h1[b * H + j] = h1;
        d_out[HID_OFF + b * H + j] = h1;
        d_out[CTX_OFF + b * H + j] = 0.0f;  // zero context for atomicAdd
    }
}

// ---------------------------------------------------------------------------
// Kernel 2: energies + softmax over batch (axis 0). grid = L blocks, 320 thr.
// (R2 version — was cheap; primes enc into L2 for ctx_kernel.)
// ---------------------------------------------------------------------------
__global__ void attn_kernel(const float* __restrict__ enc,
                            float* __restrict__ d_out) {
    int l = blockIdx.x;
    int b = threadIdx.x >> 5;
    int lane = threadIdx.x & 31;
    __shared__ float e_s[B];

    if (b < B) {
        const float4* h4 = (const float4*)(g_h1 + b * H);
        const float4* e4 = (const float4*)(enc + ((long)l * B + b) * H);
        float s = 0.f;
#pragma unroll
        for (int c = lane; c < H / 4; c += 32) s += dot4(h4[c], e4[c]);
        s = warp_sum(s);
        if (lane == 0) e_s[b] = s;
    }
    __syncthreads();
    if (threadIdx.x < B) {
        float m = -1e30f;
#pragma unroll
        for (int i = 0; i < B; i++) m = fmaxf(m, e_s[i]);
        float sum = 0.f;
#pragma unroll
        for (int i = 0; i < B; i++) sum += __expf(e_s[i] - m);
        float a = __expf(e_s[threadIdx.x] - m) / sum;
        d_out[ATTN_OFF + threadIdx.x * L + l] = a;
    }
}

// ---------------------------------------------------------------------------
// Kernel 3: context[b,h] = sum_l a[b,l]*enc[l,b,h].
// grid = B*16 = 160 blocks (b, l-chunk of 32), 512 threads (thread = h).
// Each iteration reads enc[l,b,:] as a fully coalesced 2KB row (L2-hot from
// attn_kernel); 32 unrolled independent loads => high MLP. One atomicAdd
// per element at the end: 16-deep contention per address only.
// ---------------------------------------------------------------------------
__global__ void __launch_bounds__(512)
ctx_kernel(const float* __restrict__ enc,
           float* __restrict__ d_out) {
    int b  = blockIdx.x >> 4;
    int lc = blockIdx.x & 15;
    int h  = threadIdx.x;

    __shared__ float a_s[32];
    if (threadIdx.x < 32)
        a_s[threadIdx.x] = d_out[ATTN_OFF + b * L + lc * 32 + threadIdx.x];
    __syncthreads();

    const float* ep = enc + ((long)(lc * 32) * B + b) * H + h;
    float acc = 0.f;
#pragma unroll
    for (int i = 0; i < 32; i++) {
        acc += a_s[i] * __ldg(ep + (long)i * B * H);
    }
    atomicAdd(&d_out[CTX_OFF + b * H + h], acc);
}

// ---------------------------------------------------------------------------
// Kernel 4: kb_attn. One thread per output element of the (B, L, 1954) slab.
// Reshape is a flat reinterpret: value at (b,p,1523+k) = sum_j emb_kb[idx, h]
// with f = p*431+k, kb_row = f/512, h = f%512.
// ---------------------------------------------------------------------------
__global__ void kb_kernel(const int* __restrict__ kb_inputs,
                          const float* __restrict__ emb_kb,
                          float* __restrict__ d_out) {
    unsigned t = blockIdx.x * blockDim.x + threadIdx.x;
    if (t >= (unsigned)KBA_TOT) return;
    unsigned b   = t / (L * KBW);
    unsigned rem = t % (L * KBW);
    unsigned p   = rem / KBW;
    unsigned c   = rem % KBW;
    float v = 0.0f;
    if (c >= KB_PAD) {
        unsigned f  = p * KB + (c - KB_PAD);
        unsigned kb = f >> 9;      // /512
        unsigned h  = f & 511;     // %512
        const int* idx = kb_inputs + ((long)b * KB + kb) * 3;
        v = __ldg(&emb_kb[(long)idx[0] * H + h])
          + __ldg(&emb_kb[(long)idx[1] * H + h])
          + __ldg(&emb_kb[(long)idx[2] * H + h]);
    }
    d_out[KBA_OFF + t] = v;
}

// ---------------------------------------------------------------------------
// Kernel 5: concat_output = tanh([h1, ctx] @ w_concat.T + b_concat).
// grid = H blocks, warp per batch, dot length 2H.
// ---------------------------------------------------------------------------
__global__ void concat_kernel(const float* __restrict__ w_concat,
                              const float* __restrict__ b_concat,
                              const float* __restrict__ d_out_ctx) {
    int j = blockIdx.x;
    int b = threadIdx.x >> 5;
    int lane = threadIdx.x & 31;
    if (b >= B) return;

    const float4* h4 = (const float4*)(g_h1 + b * H);
    const float4* c4 = (const float4*)(d_out_ctx + CTX_OFF + b * H);
    const float4* w4 = (const float4*)(w_concat + (long)j * 2 * H);
    float s0 = 0.f, s1 = 0.f;
#pragma unroll
    for (int c = lane; c < H / 4; c += 32) {
        s0 += dot4(h4[c], w4[c]);
        s1 += dot4(c4[c], w4[H / 4 + c]);
    }
    float s = warp_sum(s0 + s1);
    if (lane == 0) g_concat[b * H + j] = tanhf(s + b_concat[j]);
}

// ---------------------------------------------------------------------------
// Kernel 6: output = concat @ w_out.T + b_out.  (10 x 512 x 32000 fp32 GEMM)
// 1000 blocks x 256 threads. concat staged in smem; warp handles 4 vocab rows
// for all 10 batches with float4 loads.
// ---------------------------------------------------------------------------
__global__ void __launch_bounds__(256)
out_kernel(const float* __restrict__ w_out,
           const float* __restrict__ b_out,
           float* __restrict__ d_out) {
    __shared__ float cs[B * H];  // 20 KB
    for (int i = threadIdx.x; i < B * H; i += 256) cs[i] = g_concat[i];
    __syncthreads();

    int warp = threadIdx.x >> 5;
    int lane = threadIdx.x & 31;
    int v0 = blockIdx.x * 32 + warp * 4;

    // hoist bias off the epilogue critical path
    float bias[4];
#pragma unroll
    for (int i = 0; i < 4; i++) bias[i] = __ldg(&b_out[v0 + i]);

    float acc[4][B];
#pragma unroll
    for (int i = 0; i < 4; i++)
#pragma unroll
        for (int bb = 0; bb < B; bb++) acc[i][bb] = 0.f;

    const float4* w0 = (const float4*)(w_out + (long)v0 * H);
    const float4* cs4 = (const float4*)cs;

#pragma unroll
    for (int c = 0; c < 4; c++) {
        int k4 = c * 32 + lane;  // float4 index within the 512-row (0..127)
        float4 wv[4];
#pragma unroll
        for (int i = 0; i < 4; i++) wv[i] = __ldg(&w0[i * (H / 4) + k4]);
#pragma unroll
        for (int bb = 0; bb < B; bb++) {
            float4 cv = cs4[bb * (H / 4) + k4];
#pragma unroll
            for (int i = 0; i < 4; i++) {
                acc[i][bb] += wv[i].x * cv.x + wv[i].y * cv.y
                            + wv[i].z * cv.z + wv[i].w * cv.w;
            }
        }
    }

#pragma unroll
    for (int i = 0; i < 4; i++) {
#pragma unroll
        for (int bb = 0; bb < B; bb++) {
            float s = warp_sum(acc[i][bb]);
            if (lane == 0)
                d_out[OUT_OFF + (long)bb * VOCAB + v0 + i] = s + bias[i];
        }
    }
}

// ---------------------------------------------------------------------------
extern "C" void kernel_launch(void* const* d_in, const int* in_sizes, int n_in,
                              void* d_out, int out_size) {
    const int*   input_seq  = (const int*)d_in[0];
    const int*   kb_inputs  = (const int*)d_in[1];
    // d_in[2] = last_context (unused by the reference math)
    const float* last_hidden = (const float*)d_in[3];
    const float* enc        = (const float*)d_in[4];
    const float* emb        = (const float*)d_in[5];
    const float* emb_kb     = (const float*)d_in[6];
    const float* w_ih       = (const float*)d_in[7];
    const float* w_hh       = (const float*)d_in[8];
    const float* b_ih       = (const float*)d_in[9];
    const float* b_hh       = (const float*)d_in[10];
    const float* w_concat   = (const float*)d_in[11];
    const float* b_concat   = (const float*)d_in[12];
    const float* w_out      = (const float*)d_in[13];
    const float* b_out      = (const float*)d_in[14];
    float* out = (float*)d_out;

    // independent KB branch first (largest kernel; no deps)
    kb_kernel<<<(KBA_TOT + 255) / 256, 256>>>(kb_inputs, emb_kb, out);

    gru_kernel<<<H, 320>>>(input_seq, emb, last_hidden,
                           w_ih, w_hh, b_ih, b_hh, out);
    attn_kernel<<<L, 320>>>(enc, out);
    ctx_kernel<<<B * 16, 512>>>(enc, out);
    concat_kernel<<<H, 320>>>(w_concat, b_concat, out);
    out_kernel<<<VOCAB / 32, 256>>>(w_out, b_out, out);
}